// round 9
// baseline (speedup 1.0000x reference)
#include <cuda_runtime.h>
#include <math.h>

#define BB 4
#define CC 512
#define HW 1024
#define KK 64
#define NP2 8    // d2 partial count (C-split)
#define NP4 16   // agg partial count (n-split)
#define NWT 32   // wsum partial tiles

typedef unsigned long long u64;
typedef unsigned int u32;

// ---------------- scratch ----------------
__device__ float g_w1t[CC*KK];            // inv2, c-major [c][k]
__device__ float g_w2t[CC*KK];            // -2*anchor*inv2, c-major [c][k]
__device__ float g_inv[KK*CC];            // inv, k-major
__device__ float g_ck[KK];                // sum_c anchor^2*inv2
__device__ float g_d2p[NP2][BB*KK*HW];    // d2 partials, k-major
__device__ float g_nump[NP4][BB*KK*CC];   // agg partials
__device__ float g_wsp[BB*NWT*KK];        // wsum partials

// ---------------- f32x2 helpers ----------------
__device__ __forceinline__ u64 dup2(float a) {
    u64 r; asm("mov.b64 %0, {%1, %1};" : "=l"(r) : "f"(a)); return r;
}
__device__ __forceinline__ void fma2(u64& d, u64 a, u64 b) {
    asm("fma.rn.f32x2 %0, %1, %2, %0;" : "+l"(d) : "l"(a), "l"(b));
}
__device__ __forceinline__ u64 mul2(u64 a, u64 b) {
    u64 r; asm("mul.rn.f32x2 %0, %1, %2;" : "=l"(r) : "l"(a), "l"(b)); return r;
}
__device__ __forceinline__ float2 unpk(u64 a) {
    float x, y; asm("mov.b64 {%0, %1}, %2;" : "=f"(x), "=f"(y) : "l"(a));
    return make_float2(x, y);
}

// ---------------- tf32 mma helpers ----------------
__device__ __forceinline__ u32 tf32cvt(float f) {
    u32 r; asm("cvt.rna.tf32.f32 %0, %1;" : "=r"(r) : "f"(f)); return r;
}
__device__ __forceinline__ void mma_tf32(float& d0, float& d1, float& d2, float& d3,
                                         u32 a0, u32 a1, u32 a2, u32 a3,
                                         u32 b0, u32 b1) {
    asm("mma.sync.aligned.m16n8k8.row.col.f32.tf32.tf32.f32 "
        "{%0,%1,%2,%3},{%4,%5,%6,%7},{%8,%9},{%0,%1,%2,%3};"
        : "+f"(d0), "+f"(d1), "+f"(d2), "+f"(d3)
        : "r"(a0), "r"(a1), "r"(a2), "r"(a3), "r"(b0), "r"(b1));
}

// ---------------- cp.async helpers ----------------
__device__ __forceinline__ void cpa16(void* s, const void* g) {
    u32 sa = (u32)__cvta_generic_to_shared(s);
    asm volatile("cp.async.cg.shared.global [%0], [%1], 16;" :: "r"(sa), "l"(g));
}
__device__ __forceinline__ void cpcommit() {
    asm volatile("cp.async.commit_group;" ::: "memory");
}
template<int N> __device__ __forceinline__ void cpwait() {
    asm volatile("cp.async.wait_group %0;" :: "n"(N) : "memory");
}

// ---------------- K1: weights prep ----------------
__global__ void k1_prep(const float* __restrict__ anchor,
                        const float* __restrict__ sigma) {
    int k = blockIdx.x;
    int tid = threadIdx.x;
    __shared__ float red[256];
    float ck = 0.f;
    for (int c = tid; c < CC; c += 256) {
        int idx = k*CC + c;
        float s  = 1.f / (1.f + expf(-sigma[idx]));
        float iv = 1.f / (s + 1e-7f);
        float i2 = iv * iv;
        float a  = anchor[idx];
        g_w1t[c*KK + k] = i2;
        g_w2t[c*KK + k] = -2.f * a * i2;
        g_inv[idx] = iv;
        ck += a * a * i2;
    }
    red[tid] = ck; __syncthreads();
    for (int s = 128; s > 0; s >>= 1) {
        if (tid < s) red[tid] += red[tid + s];
        __syncthreads();
    }
    if (tid == 0) g_ck[k] = red[0];
}

// ---------------- K2: distance GEMM, cp.async double-buffer ----------------
// grid 256 = 4b x 8nt x 8cs, 256 thr. Block: 64k x 128n x 64c (4 chunks of 16c).
// Thread: 8k x 4n, f32x2 along k pairs. Static smem 2 x 4288 floats = 34.3KB.
#define S2STRIDE 4288   // 16*132 (x) + 16*68 (w1) + 16*68 (w2)
__global__ void __launch_bounds__(256, 2) k2_dist(const float* __restrict__ x) {
    __shared__ float sm2[2][S2STRIDE];
    int bid = blockIdx.x;
    int cs = bid & 7;
    int nt = (bid >> 3) & 7;
    int b  = bid >> 6;
    int c0 = cs * 64, n0 = nt * 128;

    int tid = threadIdx.x;
    int kr = tid >> 5;     // warp-uniform -> k0 = kr*8
    int nr = tid & 31;     // n = n0 + nr*4 + {0..3}
    int k0 = kr * 8;

    u64 acc[4][4];         // [k-pair][n]
#pragma unroll
    for (int i = 0; i < 4; i++)
#pragma unroll
        for (int j = 0; j < 4; j++) acc[i][j] = 0ull;

    auto fill = [&](int s, int cc) {
        float* xs = sm2[s];
        float* w1 = xs + 16*132;
        float* w2 = w1 + 16*68;
#pragma unroll
        for (int l = 0; l < 2; l++) {
            int slot = tid + l * 256;            // 512 f4 slots: 16c x 32 n-f4
            int row = slot >> 5;
            int col = (slot & 31) << 2;
            cpa16(&xs[row*132 + col], &x[(b*CC + c0 + cc + row)*HW + n0 + col]);
        }
        {
            int rc = tid >> 4;                   // 256 f4 slots each
            int kk = (tid & 15) << 2;
            cpa16(&w1[rc*68 + kk], &g_w1t[(c0 + cc + rc)*KK + kk]);
            cpa16(&w2[rc*68 + kk], &g_w2t[(c0 + cc + rc)*KK + kk]);
        }
        cpcommit();
    };

    auto comp = [&](int s) {
        float* xs = sm2[s];
        float* w1 = xs + 16*132;
        float* w2 = w1 + 16*68;
#pragma unroll
        for (int c = 0; c < 16; c++) {
            float4 xa = *(const float4*)&xs[c*132 + nr*4];
            ulonglong2 w1a = *(const ulonglong2*)&w1[c*68 + k0];
            ulonglong2 w1b = *(const ulonglong2*)&w1[c*68 + k0 + 4];
            ulonglong2 w2a = *(const ulonglong2*)&w2[c*68 + k0];
            ulonglong2 w2b = *(const ulonglong2*)&w2[c*68 + k0 + 4];
            u64 w1p[4] = {w1a.x, w1a.y, w1b.x, w1b.y};
            u64 w2p[4] = {w2a.x, w2a.y, w2b.x, w2b.y};
            float xn[4] = {xa.x, xa.y, xa.z, xa.w};
#pragma unroll
            for (int j = 0; j < 4; j++) {
                u64 xd = dup2(xn[j]);
                u64 xq = mul2(xd, xd);
#pragma unroll
                for (int kp = 0; kp < 4; kp++) {
                    fma2(acc[kp][j], xq, w1p[kp]);
                    fma2(acc[kp][j], xd, w2p[kp]);
                }
            }
        }
    };

    // 4 chunks of 16c, double-buffered
    fill(0, 0);
    fill(1, 16); cpwait<1>(); __syncthreads(); comp(0); __syncthreads();
    fill(0, 32); cpwait<1>(); __syncthreads(); comp(1); __syncthreads();
    fill(1, 48); cpwait<1>(); __syncthreads(); comp(0); __syncthreads();
                 cpwait<0>(); __syncthreads(); comp(1);

    // store 8k x 4n, k-major coalesced
#pragma unroll
    for (int kp = 0; kp < 4; kp++) {
        float2 p0 = unpk(acc[kp][0]), p1 = unpk(acc[kp][1]);
        float2 p2 = unpk(acc[kp][2]), p3 = unpk(acc[kp][3]);
        int klo = k0 + 2*kp;
        int base = (b*KK + klo)*HW + n0 + nr*4;
        *(float4*)&g_d2p[cs][base]      = make_float4(p0.x, p1.x, p2.x, p3.x);
        *(float4*)&g_d2p[cs][base + HW] = make_float4(p0.y, p1.y, p2.y, p3.y);
    }
}

// ---------------- K23: partial reduce + softmax + wsum partials ----------------
// grid 128 = 4b x 32 tiles(32n), 512 thr.
__global__ void __launch_bounds__(512, 2) k23(float* __restrict__ soft_out) {
    int b    = blockIdx.x >> 5;
    int tile = blockIdx.x & 31;
    int n0   = tile * 32;
    int tid  = threadIdx.x;
    __shared__ float sm[64][36];

    {
        int k  = tid >> 3;
        int n4 = (tid & 7) << 2;
        int base = (b*KK + k)*HW + n0 + n4;
        float4 s = make_float4(0.f, 0.f, 0.f, 0.f);
#pragma unroll
        for (int p = 0; p < NP2; p++) {
            float4 v = *(const float4*)&g_d2p[p][base];
            s.x += v.x; s.y += v.y; s.z += v.z; s.w += v.w;
        }
        float ck = g_ck[k];
        s.x = -0.5f*(s.x + ck); s.y = -0.5f*(s.y + ck);
        s.z = -0.5f*(s.z + ck); s.w = -0.5f*(s.w + ck);
        *(float4*)&sm[k][n4] = s;
    }
    __syncthreads();

    {
        int n   = tid >> 4;
        int sub = tid & 15;
        float v[4];
        float mx = -3.4e38f;
#pragma unroll
        for (int i = 0; i < 4; i++) {
            v[i] = sm[sub + 16*i][n];
            mx = fmaxf(mx, v[i]);
        }
#pragma unroll
        for (int m = 1; m < 16; m <<= 1)
            mx = fmaxf(mx, __shfl_xor_sync(0xffffffffu, mx, m));
        float s = 0.f;
#pragma unroll
        for (int i = 0; i < 4; i++) { v[i] = __expf(v[i] - mx); s += v[i]; }
#pragma unroll
        for (int m = 1; m < 16; m <<= 1)
            s += __shfl_xor_sync(0xffffffffu, s, m);
        float is = 1.f / s;
#pragma unroll
        for (int i = 0; i < 4; i++)
            sm[sub + 16*i][n] = v[i] * is;
    }
    __syncthreads();

    {
        int k  = tid >> 3;
        int n4 = (tid & 7) << 2;
        *(float4*)&soft_out[(b*KK + k)*HW + n0 + n4] = *(const float4*)&sm[k][n4];
    }
    {
        int k   = tid >> 3;
        int sub = tid & 7;
        float w = 0.f;
#pragma unroll
        for (int j = 0; j < 4; j++) w += sm[k][sub*4 + j];
#pragma unroll
        for (int m = 1; m < 8; m <<= 1)
            w += __shfl_xor_sync(0xffffffffu, w, m);
        if (sub == 0) g_wsp[(b*NWT + tile)*KK + k] = w;
    }
}

// ---------------- K4: aggregation GEMM, tf32 mma + cp.async double-buffer ----------------
// grid 256 = 4b x 4ct x 16ns, 256 thr. Block: 64k x 128c x 64n (4 chunks of 16n).
// Warp: 64k x 16c. Static smem 2 x 3840 floats = 30.7KB -> 2 blocks/SM, full wave.
// Pitch 20 words: frag banks (20g + t) mod 32 all distinct -> conflict-free.
#define S4STRIDE 3840   // 64*20 + 128*20
__global__ void __launch_bounds__(256, 2) k4_agg(const float* __restrict__ x,
                                                 const float* __restrict__ soft) {
    __shared__ float sm4[2][S4STRIDE];
    int bid = blockIdx.x;
    int ns = bid & 15;
    int ct = (bid >> 4) & 3;
    int b  = bid >> 6;
    int n0 = ns * 64;
    int cb = ct * 128;

    int tid  = threadIdx.x;
    int w    = tid >> 5;          // warp -> c = cb + w*16
    int lane = tid & 31;
    int g    = lane >> 2;
    int t    = lane & 3;

    float d[4][2][4];
#pragma unroll
    for (int mt = 0; mt < 4; mt++)
#pragma unroll
        for (int j = 0; j < 2; j++)
#pragma unroll
            for (int r = 0; r < 4; r++) d[mt][j][r] = 0.f;

    auto fill = [&](int s, int chunk) {
        float* As = sm4[s];
        float* Bs = As + 64*20;
        int nc = chunk * 16;
        {
            int k  = tid >> 2;               // 256 f4: 64k x 4 n-f4
            int f4 = (tid & 3) << 2;
            cpa16(&As[k*20 + f4], &soft[(b*KK + k)*HW + n0 + nc + f4]);
        }
#pragma unroll
        for (int l = 0; l < 2; l++) {
            int slot = tid + l * 256;        // 512 f4: 128c x 4 n-f4
            int c  = slot >> 2;
            int f4 = (slot & 3) << 2;
            cpa16(&Bs[c*20 + f4], &x[(b*CC + cb + c)*HW + n0 + nc + f4]);
        }
        cpcommit();
    };

    auto comp = [&](int s) {
        float* As = sm4[s];
        float* Bs = As + 64*20;
#pragma unroll
        for (int ks = 0; ks < 2; ks++) {
            int col = ks*8 + t;
            u32 a0[4], a1[4], a2[4], a3[4];
#pragma unroll
            for (int mt = 0; mt < 4; mt++) {
                a0[mt] = tf32cvt(As[(mt*16 + g)*20     + col]);
                a1[mt] = tf32cvt(As[(mt*16 + g + 8)*20 + col]);
                a2[mt] = tf32cvt(As[(mt*16 + g)*20     + col + 4]);
                a3[mt] = tf32cvt(As[(mt*16 + g + 8)*20 + col + 4]);
            }
#pragma unroll
            for (int j = 0; j < 2; j++) {
                u32 b0 = tf32cvt(Bs[(w*16 + j*8 + g)*20 + col]);
                u32 b1 = tf32cvt(Bs[(w*16 + j*8 + g)*20 + col + 4]);
#pragma unroll
                for (int mt = 0; mt < 4; mt++)
                    mma_tf32(d[mt][j][0], d[mt][j][1], d[mt][j][2], d[mt][j][3],
                             a0[mt], a1[mt], a2[mt], a3[mt], b0, b1);
            }
        }
    };

    // 4 chunks of 16n, double-buffered
    fill(0, 0);
    fill(1, 1); cpwait<1>(); __syncthreads(); comp(0); __syncthreads();
    fill(0, 2); cpwait<1>(); __syncthreads(); comp(1); __syncthreads();
    fill(1, 3); cpwait<1>(); __syncthreads(); comp(0); __syncthreads();
                cpwait<0>(); __syncthreads(); comp(1);

#pragma unroll
    for (int mt = 0; mt < 4; mt++)
#pragma unroll
        for (int j = 0; j < 2; j++) {
            int c = cb + w*16 + j*8 + 2*t;
            int k = mt*16 + g;
            *(float2*)&g_nump[ns][(b*KK + k)*CC + c]     = make_float2(d[mt][j][0], d[mt][j][1]);
            *(float2*)&g_nump[ns][(b*KK + k + 8)*CC + c] = make_float2(d[mt][j][2], d[mt][j][3]);
        }
}

// ---------------- K5: epilogue + row normalize + folded flat normalize ----------------
__global__ void k5_epilogue(const float* __restrict__ anchor,
                            float* __restrict__ out) {
    int bk = blockIdx.x;
    int k  = bk & 63;
    int b  = bk >> 6;
    int tid = threadIdx.x;
    __shared__ float red[256];

    float ws = 0.f;
#pragma unroll
    for (int p = 0; p < NWT; p++) ws += g_wsp[(b*NWT + p)*KK + k];

    float invden = 1.f / (ws + 1e-7f);
    float node[2];
    float sq = 0.f;
#pragma unroll
    for (int l = 0; l < 2; l++) {
        int c = tid + l * 256;
        int gi = bk * CC + c;
        float num = 0.f;
#pragma unroll
        for (int p = 0; p < NP4; p++) num += g_nump[p][gi];
        num = (num - ws * anchor[k*CC + c]) * g_inv[k*CC + c];
        float nd = num * invden;
        node[l] = nd;
        sq += nd * nd;
    }
    red[tid] = sq; __syncthreads();
    for (int s = 128; s > 0; s >>= 1) {
        if (tid < s) red[tid] += red[tid + s];
        __syncthreads();
    }
    float total = red[0];
    float scale = 0.125f / fmaxf(sqrtf(total), 1e-12f);
#pragma unroll
    for (int l = 0; l < 2; l++)
        out[bk * CC + tid + l * 256] = node[l] * scale;
}

// ---------------- launch ----------------
extern "C" void kernel_launch(void* const* d_in, const int* in_sizes, int n_in,
                              void* d_out, int out_size) {
    const float* x      = (const float*)d_in[0];
    const float* anchor = (const float*)d_in[1];
    const float* sigma  = (const float*)d_in[2];
    float* out = (float*)d_out;
    float* nodes_out = out;                 // B*K*C floats
    float* soft_out  = out + BB*KK*CC;      // B*K*HW floats

    k1_prep    <<<KK, 256>>>(anchor, sigma);
    k2_dist    <<<256, 256>>>(x);
    k23        <<<128, 512>>>(soft_out);
    k4_agg     <<<256, 256>>>(x, soft_out);
    k5_epilogue<<<BB*KK, 256>>>(anchor, nodes_out);
}